// round 2
// baseline (speedup 1.0000x reference)
#include <cuda_runtime.h>
#include <math.h>

#define IMG 256
#define MAX_R 64
#define N_AG 2047
#define N_OB 2048
#define N_ENT (N_AG + N_OB)
#define FOVH 0.7853981633974483f   /* pi/4 = FOV/2 */

#define NSTRIPE 32
#define STRIPE_SHIFT 3             /* 8 columns per stripe */
#define BIN_CAP 4096               /* max records per stripe (hard upper bound N_ENT) */

// Record: {pxi, pr*pr, depth_bits, pad}
__device__ int4 g_bin[NSTRIPE * BIN_CAP];
__device__ int  g_cnt[NSTRIPE];

__global__ void zero_kernel() {
    if (threadIdx.x < NSTRIPE) g_cnt[threadIdx.x] = 0;
}

__global__ void bin_kernel(const float* __restrict__ agent,
                           const float* __restrict__ goal,
                           const float* __restrict__ others,
                           const float* __restrict__ obs) {
    int e = blockIdx.x * blockDim.x + threadIdx.x;
    if (e >= N_ENT) return;

    float ax = agent[0], ay = agent[1];
    float vx = goal[0] - ax, vy = goal[1] - ay;
    float inv = 1.0f / (sqrtf(vx * vx + vy * vy) + 1e-8f);
    vx *= inv; vy *= inv;
    float c = vy, s = vx;

    float ex, ey, r, h;
    if (e < N_AG) {
        ex = others[2 * e];
        ey = others[2 * e + 1];
        r  = 0.05f;
        h  = 0.2f;
    } else {
        int o = e - N_AG;
        ex = obs[3 * o];
        ey = obs[3 * o + 1];
        r  = obs[3 * o + 2];
        h  = 0.5f;
    }

    float rx = ex - ax, ry = ey - ay;
    float camx =  c * rx + s * ry;
    float camy = -s * rx + c * ry;
    float dist = sqrtf(camx * camx + camy * camy);
    float angle = atan2f(camx, camy);

    if (!((camy >= 0.0f) && (dist <= 3.0f) && (fabsf(angle) <= FOVH))) return;

    float pixel_x = angle / FOVH * 0.5f;
    int pxi = (int)floorf((pixel_x + 0.5f) * (float)IMG);
    int pr  = (int)floorf(r / (dist + 1e-8f) * (float)IMG * 0.5f);
    pr = min(max(pr, 1), MAX_R);

    float depth = fminf(dist / 3.0f, 1.0f) * (1.0f - h * 0.3f);
    depth = fmaxf(depth, 0.0f);

    int lo = pxi - pr, hi = pxi + pr;
    if (hi < 0 || lo >= IMG) return;
    lo = max(lo, 0); hi = min(hi, IMG - 1);
    int s0 = lo >> STRIPE_SHIFT, s1 = hi >> STRIPE_SHIFT;

    int4 rec;
    rec.x = pxi;
    rec.y = pr * pr;
    rec.z = __float_as_int(depth);
    rec.w = 0;
    for (int st = s0; st <= s1; st++) {
        int idx = atomicAdd(&g_cnt[st], 1);
        g_bin[st * BIN_CAP + idx] = rec;
    }
}

__global__ void paint_kernel(float* __restrict__ out) {
    int col = blockIdx.x;
    int row = threadIdx.x;
    int st  = col >> STRIPE_SHIFT;
    int n   = g_cnt[st];
    const int4* __restrict__ bin = &g_bin[st * BIN_CAP];

    int dy = row - IMG / 2;
    int d2 = dy * dy;
    float m = 1.0f;

    #pragma unroll 4
    for (int e = 0; e < n; e++) {
        int4 rec = __ldg(&bin[e]);
        int dx = col - rec.x;
        if (dx * dx + d2 <= rec.y) m = fminf(m, __int_as_float(rec.z));
    }
    out[row * IMG + col] = m;
}

extern "C" void kernel_launch(void* const* d_in, const int* in_sizes, int n_in,
                              void* d_out, int out_size) {
    const float* agent  = (const float*)d_in[0];
    const float* goal   = (const float*)d_in[1];
    const float* others = (const float*)d_in[2];
    const float* obs    = (const float*)d_in[3];
    float* out          = (float*)d_out;

    zero_kernel<<<1, NSTRIPE>>>();
    bin_kernel<<<(N_ENT + 255) / 256, 256>>>(agent, goal, others, obs);
    paint_kernel<<<IMG, IMG>>>(out);
}

// round 3
// speedup vs baseline: 1.5970x; 1.5970x over previous
#include <cuda_runtime.h>
#include <math.h>

#define IMG 256
#define MAX_R 64
#define N_AG 2047
#define N_OB 2048
#define N_ENT 4095
#define FOVH 0.7853981633974483f   /* pi/4 = FOV/2 */
#define THREADS 256
#define COLS_PER_BLOCK 2
#define NBLOCKS (IMG / COLS_PER_BLOCK)   /* 128 blocks, single wave on 148 SMs */

__global__ __launch_bounds__(THREADS, 1)
void render_kernel(const float* __restrict__ agent,
                   const float* __restrict__ goal,
                   const float* __restrict__ others,
                   const float* __restrict__ obs,
                   float* __restrict__ out) {
    __shared__ uint2 s_rec[N_ENT];   /* {pxi<<16 | pr*pr, depth_bits} */
    __shared__ int s_cnt;

    int tid = threadIdx.x;
    if (tid == 0) s_cnt = 0;
    __syncthreads();

    int c0 = blockIdx.x * COLS_PER_BLOCK;
    int c1 = c0 + COLS_PER_BLOCK - 1;

    /* camera basis (redundant per block; trivial) */
    float ax = agent[0], ay = agent[1];
    float vx = goal[0] - ax, vy = goal[1] - ay;
    float inv = 1.0f / (sqrtf(vx * vx + vy * vy) + 1e-8f);
    vx *= inv; vy *= inv;
    float c = vy, s = vx;

    /* Phase 1: cooperative transform + stripe filter */
    for (int e = tid; e < N_ENT; e += THREADS) {
        float ex, ey, r, h;
        if (e < N_AG) {
            ex = others[2 * e];
            ey = others[2 * e + 1];
            r  = 0.05f;
            h  = 0.2f;
        } else {
            int o = e - N_AG;
            ex = obs[3 * o];
            ey = obs[3 * o + 1];
            r  = obs[3 * o + 2];
            h  = 0.5f;
        }
        float rx = ex - ax, ry = ey - ay;
        float camx =  c * rx + s * ry;
        float camy = -s * rx + c * ry;
        float dist = sqrtf(camx * camx + camy * camy);
        float angle = atan2f(camx, camy);
        if (!((camy >= 0.0f) && (dist <= 3.0f) && (fabsf(angle) <= FOVH)))
            continue;

        float pixel_x = angle / FOVH * 0.5f;
        int pxi = (int)floorf((pixel_x + 0.5f) * (float)IMG);
        int pr  = (int)floorf(r / (dist + 1e-8f) * (float)IMG * 0.5f);
        pr = min(max(pr, 1), MAX_R);
        if (pxi + pr < c0 || pxi - pr > c1) continue;   /* disk misses stripe */

        float depth = fminf(dist / 3.0f, 1.0f) * (1.0f - h * 0.3f);
        depth = fmaxf(depth, 0.0f);

        int idx = atomicAdd(&s_cnt, 1);
        s_rec[idx] = make_uint2(((unsigned)pxi << 16) | (unsigned)(pr * pr),
                                __float_as_uint(depth));
    }
    __syncthreads();
    int n = s_cnt;

    /* Phase 2: one thread per row, 2 columns, register min accumulation */
    int row = tid;
    int dy = row - IMG / 2;
    int d2 = dy * dy;
    float m0 = 1.0f, m1 = 1.0f;

    #pragma unroll 4
    for (int e = 0; e < n; e++) {
        uint2 rec = s_rec[e];            /* broadcast LDS.64 */
        int pxi = (int)(rec.x >> 16);
        int pr2 = (int)(rec.x & 0xffffu);
        float d = __uint_as_float(rec.y);
        int dx0 = c0 - pxi;
        int dx1 = dx0 + 1;
        if (dx0 * dx0 + d2 <= pr2) m0 = fminf(m0, d);
        if (dx1 * dx1 + d2 <= pr2) m1 = fminf(m1, d);
    }

    out[row * IMG + c0]     = m0;
    out[row * IMG + c0 + 1] = m1;
}

extern "C" void kernel_launch(void* const* d_in, const int* in_sizes, int n_in,
                              void* d_out, int out_size) {
    const float* agent  = (const float*)d_in[0];
    const float* goal   = (const float*)d_in[1];
    const float* others = (const float*)d_in[2];
    const float* obs    = (const float*)d_in[3];
    float* out          = (float*)d_out;

    render_kernel<<<NBLOCKS, THREADS>>>(agent, goal, others, obs, out);
}

// round 4
// speedup vs baseline: 2.4884x; 1.5581x over previous
#include <cuda_runtime.h>
#include <math.h>

#define IMG 256
#define MAX_R 64
#define N_AG 2047
#define N_OB 2048
#define N_ENT 4095
#define FOVH 0.7853981633974483f   /* pi/4 = FOV/2 */

/* fixed-slot records: {pxi<<16 | pr*pr, depth_bits}; invalid => pxi = -30000 */
__device__ uint2 g_rec[4096];

__global__ void transform_kernel(const float* __restrict__ agent,
                                 const float* __restrict__ goal,
                                 const float* __restrict__ others,
                                 const float* __restrict__ obs) {
    int e = blockIdx.x * blockDim.x + threadIdx.x;
    if (e >= N_ENT) return;

    float ax = agent[0], ay = agent[1];
    float vx = goal[0] - ax, vy = goal[1] - ay;
    float inv = 1.0f / (sqrtf(vx * vx + vy * vy) + 1e-8f);
    vx *= inv; vy *= inv;
    float c = vy, s = vx;

    float ex, ey, r, h;
    if (e < N_AG) {
        ex = others[2 * e];
        ey = others[2 * e + 1];
        r  = 0.05f;
        h  = 0.2f;
    } else {
        int o = e - N_AG;
        ex = obs[3 * o];
        ey = obs[3 * o + 1];
        r  = obs[3 * o + 2];
        h  = 0.5f;
    }

    float rx = ex - ax, ry = ey - ay;
    float camx =  c * rx + s * ry;
    float camy = -s * rx + c * ry;
    float dist = sqrtf(camx * camx + camy * camy);
    float angle = atan2f(camx, camy);

    uint2 rec;
    if ((camy >= 0.0f) && (dist <= 3.0f) && (fabsf(angle) <= FOVH)) {
        float pixel_x = angle / FOVH * 0.5f;
        int pxi = (int)floorf((pixel_x + 0.5f) * (float)IMG);
        int pr  = (int)floorf(r / (dist + 1e-8f) * (float)IMG * 0.5f);
        pr = min(max(pr, 1), MAX_R);
        float depth = fminf(dist / 3.0f, 1.0f) * (1.0f - h * 0.3f);
        depth = fmaxf(depth, 0.0f);
        rec.x = ((unsigned)pxi << 16) | (unsigned)(pr * pr);
        rec.y = __float_as_uint(depth);
    } else {
        rec.x = ((unsigned)(-30000) << 16);   /* never overlaps any column */
        rec.y = __float_as_uint(1.0f);
    }
    g_rec[e] = rec;
}

__global__ __launch_bounds__(256)
void paint_kernel(float* __restrict__ out) {
    __shared__ uint2 s_rec[N_ENT];   /* {pr2 - dx2, depth_bits} */
    __shared__ int s_cnt;

    int tid = threadIdx.x;
    int col = blockIdx.x;
    if (tid == 0) s_cnt = 0;
    __syncthreads();

    /* Phase A: compact records overlapping this column */
    #pragma unroll 4
    for (int e = tid; e < N_ENT; e += 256) {
        uint2 g = __ldg(&g_rec[e]);
        int pxi = (int)g.x >> 16;            /* arithmetic shift recovers sign */
        int pr2 = (int)(g.x & 0xffffu);
        int dx  = col - pxi;
        int rem = pr2 - dx * dx;
        if (rem >= 0) {
            int idx = atomicAdd(&s_cnt, 1);
            s_rec[idx] = make_uint2((unsigned)rem, g.y);
        }
    }
    __syncthreads();
    int n = s_cnt;

    /* Phase B: one thread per row, register min */
    int row = tid;
    int dy = row - IMG / 2;
    int d2 = dy * dy;
    float m = 1.0f;

    #pragma unroll 4
    for (int e = 0; e < n; e++) {
        uint2 r = s_rec[e];                  /* broadcast LDS.64 */
        if (d2 <= (int)r.x) m = fminf(m, __uint_as_float(r.y));
    }
    out[row * IMG + col] = m;
}

extern "C" void kernel_launch(void* const* d_in, const int* in_sizes, int n_in,
                              void* d_out, int out_size) {
    const float* agent  = (const float*)d_in[0];
    const float* goal   = (const float*)d_in[1];
    const float* others = (const float*)d_in[2];
    const float* obs    = (const float*)d_in[3];
    float* out          = (float*)d_out;

    transform_kernel<<<32, 128>>>(agent, goal, others, obs);
    paint_kernel<<<IMG, 256>>>(out);
}

// round 5
// speedup vs baseline: 2.5552x; 1.0269x over previous
#include <cuda_runtime.h>
#include <math.h>

#define IMG 256
#define MAX_R 64
#define N_AG 2047
#define N_OB 2048
#define N_ENT 4095
#define FOVH 0.7853981633974483f   /* pi/4 = FOV/2 */
#define PTHREADS 512

/* fixed-slot records: {pxi<<16 | pr*pr, depth_bits}; invalid => pxi = -30000 */
__device__ uint2 g_rec[4096];

__global__ void transform_kernel(const float* __restrict__ agent,
                                 const float* __restrict__ goal,
                                 const float* __restrict__ others,
                                 const float* __restrict__ obs) {
    int e = blockIdx.x * blockDim.x + threadIdx.x;
    if (e >= N_ENT) return;

    float ax = agent[0], ay = agent[1];
    float vx = goal[0] - ax, vy = goal[1] - ay;
    float inv = 1.0f / (sqrtf(vx * vx + vy * vy) + 1e-8f);
    vx *= inv; vy *= inv;
    float c = vy, s = vx;

    float ex, ey, r, h;
    if (e < N_AG) {
        ex = others[2 * e];
        ey = others[2 * e + 1];
        r  = 0.05f;
        h  = 0.2f;
    } else {
        int o = e - N_AG;
        ex = obs[3 * o];
        ey = obs[3 * o + 1];
        r  = obs[3 * o + 2];
        h  = 0.5f;
    }

    float rx = ex - ax, ry = ey - ay;
    float camx =  c * rx + s * ry;
    float camy = -s * rx + c * ry;
    float dist = sqrtf(camx * camx + camy * camy);
    float angle = atan2f(camx, camy);

    uint2 rec;
    if ((camy >= 0.0f) && (dist <= 3.0f) && (fabsf(angle) <= FOVH)) {
        float pixel_x = angle / FOVH * 0.5f;
        int pxi = (int)floorf((pixel_x + 0.5f) * (float)IMG);
        int pr  = (int)floorf(r / (dist + 1e-8f) * (float)IMG * 0.5f);
        pr = min(max(pr, 1), MAX_R);
        float depth = fminf(dist / 3.0f, 1.0f) * (1.0f - h * 0.3f);
        depth = fmaxf(depth, 0.0f);
        rec.x = ((unsigned)pxi << 16) | (unsigned)(pr * pr);
        rec.y = __float_as_uint(depth);
    } else {
        rec.x = ((unsigned)(-30000) << 16);   /* never overlaps any column */
        rec.y = __float_as_uint(1.0f);
    }
    g_rec[e] = rec;
}

__global__ __launch_bounds__(PTHREADS)
void paint_kernel(float* __restrict__ out) {
    __shared__ uint2 s_rec[N_ENT];   /* {pr2 - dx2, depth_bits} */
    __shared__ int   s_cnt;
    __shared__ float s_min[PTHREADS];

    int tid = threadIdx.x;
    int col = blockIdx.x;
    unsigned lane = tid & 31;
    if (tid == 0) s_cnt = 0;
    __syncthreads();

    /* Phase A: compact records overlapping this column (warp-aggregated) */
    #pragma unroll
    for (int k = 0; k < 8; k++) {
        int e = tid + k * PTHREADS;
        bool hit = false;
        unsigned rem = 0, db = 0;
        if (e < N_ENT) {
            uint2 g = __ldg(&g_rec[e]);
            int pxi = (int)g.x >> 16;            /* arithmetic shift: sign ok */
            int pr2 = (int)(g.x & 0xffffu);
            int dx  = col - pxi;
            int r   = pr2 - dx * dx;
            hit = (r >= 0);
            rem = (unsigned)r;
            db  = g.y;
        }
        unsigned m = __ballot_sync(0xffffffffu, hit);
        if (hit) {
            int leader = __ffs(m) - 1;
            int base = 0;
            if ((int)lane == leader) base = atomicAdd(&s_cnt, __popc(m));
            base = __shfl_sync(m, base, leader);
            int pos = base + __popc(m & ((1u << lane) - 1));
            s_rec[pos] = make_uint2(rem, db);
        }
    }
    __syncthreads();
    int n = s_cnt;

    /* Phase B: two threads per row, each scans half the records */
    int row  = tid & 255;
    int half = tid >> 8;
    int dy = row - IMG / 2;
    int d2 = dy * dy;
    float mv = 1.0f;

    #pragma unroll 4
    for (int e = half; e < n; e += 2) {
        uint2 r = s_rec[e];                      /* broadcast LDS.64 */
        if (d2 <= (int)r.x) mv = fminf(mv, __uint_as_float(r.y));
    }
    s_min[tid] = mv;
    __syncthreads();

    if (tid < 256)
        out[row * IMG + col] = fminf(s_min[tid], s_min[tid + 256]);
}

extern "C" void kernel_launch(void* const* d_in, const int* in_sizes, int n_in,
                              void* d_out, int out_size) {
    const float* agent  = (const float*)d_in[0];
    const float* goal   = (const float*)d_in[1];
    const float* others = (const float*)d_in[2];
    const float* obs    = (const float*)d_in[3];
    float* out          = (float*)d_out;

    transform_kernel<<<64, 64>>>(agent, goal, others, obs);
    paint_kernel<<<IMG, PTHREADS>>>(out);
}